// round 4
// baseline (speedup 1.0000x reference)
#include <cuda_runtime.h>
#include <cuda_fp16.h>
#include <cstdint>

// ---------------------------------------------------------------------------
// Problem constants
// ---------------------------------------------------------------------------
#define BATCH    8192
#define HIDDEN   2048
#define NQ       16
#define HALF_DIM 1024

// GEMM tiling: CTA 128x128, 4 warps (2x2), warp tile 64x64, 2 CTAs/SM
#define BM      128
#define BN      128
#define KC      64                      // fp16 K elements per chunk = 128 bytes/row
#define NCHUNK  (HIDDEN / KC)           // 32
#define STAGES  3
#define THREADS 128

#define A_STAGE_BYTES (BM * KC * 2)     // 16384
#define B_STAGE_BYTES (BN * KC * 2)     // 16384
#define STAGE_BYTES   (A_STAGE_BYTES + B_STAGE_BYTES)  // 32768

// SMEM layout (dynamic)
#define OFF_B1    0                     // 128 floats
#define OFF_W2    512                   // 128 floats
#define OFF_STAGE 1024
#define SMEM_BYTES (OFF_STAGE + STAGES * STAGE_BYTES)   // 99328 (x2 CTAs = 194KB/SM)

// fp16 scratch (device globals: allocation-free scratch per harness rules)
__device__ __align__(1024) __half g_Xh[(size_t)BATCH * HIDDEN];            // 32 MB
__device__ __align__(1024) __half g_Wh[(size_t)NQ * HALF_DIM * HIDDEN];   // 64 MB

// ---------------------------------------------------------------------------
// Helpers
// ---------------------------------------------------------------------------
__device__ __forceinline__ uint32_t smem_u32(const void* p) {
    uint32_t a;
    asm("{ .reg .u64 t; cvta.to.shared.u64 t, %1; cvt.u32.u64 %0, t; }"
        : "=r"(a) : "l"(p));
    return a;
}

#define SW128(off) ((off) ^ (((off) >> 3) & 0x70))

__device__ __forceinline__ void cp_async16(uint32_t dst, const void* src) {
    asm volatile("cp.async.cg.shared.global [%0], [%1], 16;" :: "r"(dst), "l"(src) : "memory");
}
__device__ __forceinline__ void cp_async_commit() {
    asm volatile("cp.async.commit_group;" ::: "memory");
}
template <int N>
__device__ __forceinline__ void cp_async_wait() {
    asm volatile("cp.async.wait_group %0;" :: "n"(N) : "memory");
}

__device__ __forceinline__ void ldsm4(uint32_t* r, uint32_t addr) {
    asm volatile("ldmatrix.sync.aligned.m8n8.x4.shared.b16 {%0,%1,%2,%3}, [%4];"
        : "=r"(r[0]), "=r"(r[1]), "=r"(r[2]), "=r"(r[3]) : "r"(addr));
}

__device__ __forceinline__ void mma16816(float* c, const uint32_t* a, const uint32_t* b) {
    asm volatile(
        "mma.sync.aligned.m16n8k16.row.col.f32.f16.f16.f32 "
        "{%0,%1,%2,%3}, {%4,%5,%6,%7}, {%8,%9}, {%0,%1,%2,%3};"
        : "+f"(c[0]), "+f"(c[1]), "+f"(c[2]), "+f"(c[3])
        : "r"(a[0]), "r"(a[1]), "r"(a[2]), "r"(a[3]), "r"(b[0]), "r"(b[1]));
}

// ---------------------------------------------------------------------------
// Prepass kernels
// ---------------------------------------------------------------------------
__global__ void prep_x_kernel(const float4* __restrict__ x, int n4) {
    int i = blockIdx.x * blockDim.x + threadIdx.x;
    if (i < n4) {
        float4 v = x[i];
        __half2 lo = __floats2half2_rn(v.x, v.y);
        __half2 hi = __floats2half2_rn(v.z, v.w);
        union { __half2 h; unsigned u; } a, b;
        a.h = lo; b.h = hi;
        reinterpret_cast<uint2*>(g_Xh)[i] = make_uint2(a.u, b.u);
    }
}

// W1[q][h][n] (n contiguous) -> Wh[q][n][h] (h contiguous), rounded to fp16
__global__ void prep_w_kernel(const float* __restrict__ W1) {
    __shared__ float tile[32][33];
    int q  = blockIdx.z;
    int n0 = blockIdx.x * 32;
    int h0 = blockIdx.y * 32;
    const float* src = W1 + (size_t)q * HIDDEN * HALF_DIM;
#pragma unroll
    for (int r = 0; r < 4; r++) {
        int row = threadIdx.y + r * 8;  // h offset
        tile[row][threadIdx.x] = src[(size_t)(h0 + row) * HALF_DIM + n0 + threadIdx.x];
    }
    __syncthreads();
    __half* dst = g_Wh + (size_t)q * HALF_DIM * HIDDEN;
#pragma unroll
    for (int r = 0; r < 4; r++) {
        int row = threadIdx.y + r * 8;  // n offset
        dst[(size_t)(n0 + row) * HIDDEN + h0 + threadIdx.x] = __float2half_rn(tile[threadIdx.x][row]);
    }
}

__global__ void init_out_kernel(float* __restrict__ out, const float* __restrict__ b2) {
    int i = blockIdx.x * blockDim.x + threadIdx.x;
    if (i < BATCH * NQ) out[i] = b2[i & (NQ - 1)];
}

// ---------------------------------------------------------------------------
// Main GEMM + fused GELU/GEMV epilogue (mma.sync / HMMA path)
// ---------------------------------------------------------------------------
__device__ __forceinline__ void load_stage(uint32_t sb, int s, int chunk,
                                           const __half* Ab, const __half* Bb, int tid) {
    uint32_t a0 = sb + OFF_STAGE + s * STAGE_BYTES;
    uint32_t b0 = a0 + A_STAGE_BYTES;
    const char* asrc = (const char*)Ab + (size_t)chunk * (KC * 2);
    const char* bsrc = (const char*)Bb + (size_t)chunk * (KC * 2);
#pragma unroll
    for (int t = 0; t < 8; t++) {
        int o = tid + t * THREADS;      // 0..1023
        int row = o >> 3;               // 0..127
        int kg  = o & 7;                // 16B group within 128B row
        uint32_t off = row * 128 + kg * 16;
        uint32_t sw = SW128(off);
        size_t gsrc = (size_t)row * (HIDDEN * 2) + kg * 16;
        cp_async16(a0 + sw, asrc + gsrc);
        cp_async16(b0 + sw, bsrc + gsrc);
    }
}

__global__ void __launch_bounds__(THREADS, 2)
gemm_kernel(const float* __restrict__ b1, const float* __restrict__ W2,
            float* __restrict__ out) {
    extern __shared__ char smem[];
    const uint32_t sb = smem_u32(smem);
    const int tid = threadIdx.x;
    const int wid = tid >> 5;
    const int lid = tid & 31;
    const int wm  = wid >> 1;           // M slab (64 rows), 0..1
    const int wn  = wid & 1;            // N slab (64 cols), 0..1

    // Supertile swizzle: 8(M) x 16(N) CTAs per 128-CTA group; 8x8 groups.
    int cta    = blockIdx.x;
    int super  = cta >> 7;
    int within = cta & 127;
    int m_tile = (super & 7) * 8 + (within & 7);    // 0..63
    int n_tile = (super >> 3) * 16 + (within >> 3); // 0..127
    int m0     = m_tile * BM;
    int wrow0  = n_tile * BN;                       // = q*1024 + nn
    int q      = n_tile >> 3;
    int nn     = (n_tile & 7) * BN;

    // Epilogue params into smem
    if (tid < 128) {
        ((float*)(smem + OFF_B1))[tid] = b1[q * HALF_DIM + nn + tid];
        ((float*)(smem + OFF_W2))[tid] = W2[q * HALF_DIM + nn + tid];
    }

    const __half* Ab = g_Xh + (size_t)m0 * HIDDEN;
    const __half* Bb = g_Wh + (size_t)wrow0 * HIDDEN;

    // Prologue: fill STAGES-1 stages
#pragma unroll
    for (int s = 0; s < STAGES - 1; s++) {
        load_stage(sb, s, s, Ab, Bb, tid);
        cp_async_commit();
    }

    // acc[mi][ni][4]: mi = 4 x m16 slabs, ni = 8 x n8 slabs (warp tile 64x64)
    float acc[4][8][4];
#pragma unroll
    for (int mi = 0; mi < 4; mi++)
#pragma unroll
        for (int ni = 0; ni < 8; ni++)
#pragma unroll
            for (int e = 0; e < 4; e++) acc[mi][ni][e] = 0.0f;

    // ldmatrix lane-address components (bytes, pre-swizzle)
    const int a_row_l = lid & 15;                       // m row within 16
    const int a_kb_l  = (lid >> 4) << 4;                // 0 or 16 bytes
    const int b_row_l = ((lid >> 4) << 3) + (lid & 7);  // n row within 16
    const int b_kb_l  = ((lid >> 3) & 1) << 4;          // 0 or 16 bytes

    for (int i = 0; i < NCHUNK; i++) {
        if (i == NCHUNK - 1) cp_async_wait<0>();
        else                 cp_async_wait<STAGES - 2>();
        __syncthreads();

        int jn = i + STAGES - 1;
        if (jn < NCHUNK) {
            load_stage(sb, jn % STAGES, jn, Ab, Bb, tid);
            cp_async_commit();
        }

        uint32_t a_base = sb + OFF_STAGE + (i % STAGES) * STAGE_BYTES;
        uint32_t b_base = a_base + A_STAGE_BYTES;

#pragma unroll
        for (int kk = 0; kk < 4; kk++) {   // 4 x k16 steps per 64-K chunk
            // A fragments: 64 rows (4 x 16)
            uint32_t afr[4][4];
#pragma unroll
            for (int mi = 0; mi < 4; mi++) {
                uint32_t off = (uint32_t)(wm * 64 + mi * 16 + a_row_l) * 128
                             + (uint32_t)(kk * 32 + a_kb_l);
                ldsm4(afr[mi], a_base + SW128(off));
            }
            // B fragments: 64 cols (4 x 16)
            uint32_t bfr[4][4];
#pragma unroll
            for (int nj = 0; nj < 4; nj++) {
                uint32_t off = (uint32_t)(wn * 64 + nj * 16 + b_row_l) * 128
                             + (uint32_t)(kk * 32 + b_kb_l);
                ldsm4(bfr[nj], b_base + SW128(off));
            }
            // 32 MMAs per k-step
#pragma unroll
            for (int mi = 0; mi < 4; mi++)
#pragma unroll
                for (int nj = 0; nj < 4; nj++) {
                    mma16816(acc[mi][nj * 2 + 0], afr[mi], &bfr[nj][0]);
                    mma16816(acc[mi][nj * 2 + 1], afr[mi], &bfr[nj][2]);
                }
        }
    }
    __syncthreads();

    // Epilogue: h = acc + b1; gelu(h) = h * Phi(h); dot with W2; quad-reduce; atomic add.
    const float* b1s = (const float*)(smem + OFF_B1);
    const float* w2s = (const float*)(smem + OFF_W2);
#pragma unroll
    for (int mi = 0; mi < 4; mi++) {
#pragma unroll
        for (int rh = 0; rh < 2; rh++) {
            float v = 0.0f;
#pragma unroll
            for (int ni = 0; ni < 8; ni++) {
                int ncol = wn * 64 + ni * 8 + 2 * (lid & 3);
#pragma unroll
                for (int e = 0; e < 2; e++) {
                    float h = acc[mi][ni][rh * 2 + e] + b1s[ncol + e];
                    v += h * normcdff(h) * w2s[ncol + e];
                }
            }
            v += __shfl_xor_sync(0xFFFFFFFFu, v, 1);
            v += __shfl_xor_sync(0xFFFFFFFFu, v, 2);
            if ((lid & 3) == 0) {
                int mrow = m0 + wm * 64 + mi * 16 + rh * 8 + (lid >> 2);
                atomicAdd(out + (size_t)mrow * NQ + q, v);
            }
        }
    }
}

// ---------------------------------------------------------------------------
// Launch
// ---------------------------------------------------------------------------
extern "C" void kernel_launch(void* const* d_in, const int* in_sizes, int n_in,
                              void* d_out, int out_size) {
    const float* x  = (const float*)d_in[0];
    const float* W1 = (const float*)d_in[1];
    const float* b1 = (const float*)d_in[2];
    const float* W2 = (const float*)d_in[3];
    const float* b2 = (const float*)d_in[4];
    float* out = (float*)d_out;
    (void)in_sizes; (void)n_in; (void)out_size;

    cudaFuncSetAttribute(gemm_kernel, cudaFuncAttributeMaxDynamicSharedMemorySize, SMEM_BYTES);

    int n4 = BATCH * HIDDEN / 4;
    prep_x_kernel<<<(n4 + 255) / 256, 256>>>((const float4*)x, n4);
    prep_w_kernel<<<dim3(HALF_DIM / 32, HIDDEN / 32, NQ), dim3(32, 8)>>>(W1);
    init_out_kernel<<<(BATCH * NQ + 255) / 256, 256>>>(out, b2);
    gemm_kernel<<<(BATCH / BM) * (NQ * HALF_DIM / BN), THREADS, SMEM_BYTES>>>(b1, W2, out);
}

// round 5
// speedup vs baseline: 1.1724x; 1.1724x over previous
#include <cuda_runtime.h>
#include <cuda_fp16.h>
#include <cstdint>

// ---------------------------------------------------------------------------
// Problem constants
// ---------------------------------------------------------------------------
#define BATCH    8192
#define HIDDEN   2048
#define NQ       16
#define HALF_DIM 1024

// GEMM tiling: CTA 128(M)x64(N), 4 warps (2Mx2N of 64x32), 2-stage, 4 CTAs/SM
#define BM      128
#define BN      64
#define KC      64                      // fp16 K elements per chunk = 128 bytes/row
#define NCHUNK  (HIDDEN / KC)           // 32
#define STAGES  2
#define THREADS 128

#define A_STAGE_BYTES (BM * KC * 2)     // 16384
#define B_STAGE_BYTES (BN * KC * 2)     // 8192
#define STAGE_BYTES   (A_STAGE_BYTES + B_STAGE_BYTES)  // 24576

// SMEM layout (dynamic)
#define OFF_B1    0                     // 64 floats
#define OFF_W2    256                   // 64 floats
#define OFF_STAGE 1024
#define SMEM_BYTES (OFF_STAGE + STAGES * STAGE_BYTES)   // 50176 (x4 CTAs = 196KB/SM)

// fp16 scratch (device globals: allocation-free scratch per harness rules)
__device__ __align__(1024) __half g_Xh[(size_t)BATCH * HIDDEN];            // 32 MB
__device__ __align__(1024) __half g_Wh[(size_t)NQ * HALF_DIM * HIDDEN];   // 64 MB

// ---------------------------------------------------------------------------
// Helpers
// ---------------------------------------------------------------------------
__device__ __forceinline__ uint32_t smem_u32(const void* p) {
    uint32_t a;
    asm("{ .reg .u64 t; cvta.to.shared.u64 t, %1; cvt.u32.u64 %0, t; }"
        : "=r"(a) : "l"(p));
    return a;
}

#define SW128(off) ((off) ^ (((off) >> 3) & 0x70))

__device__ __forceinline__ void cp_async16(uint32_t dst, const void* src) {
    asm volatile("cp.async.cg.shared.global [%0], [%1], 16;" :: "r"(dst), "l"(src) : "memory");
}
__device__ __forceinline__ void cp_async_commit() {
    asm volatile("cp.async.commit_group;" ::: "memory");
}
template <int N>
__device__ __forceinline__ void cp_async_wait() {
    asm volatile("cp.async.wait_group %0;" :: "n"(N) : "memory");
}

__device__ __forceinline__ void ldsm4(uint32_t* r, uint32_t addr) {
    asm volatile("ldmatrix.sync.aligned.m8n8.x4.shared.b16 {%0,%1,%2,%3}, [%4];"
        : "=r"(r[0]), "=r"(r[1]), "=r"(r[2]), "=r"(r[3]) : "r"(addr));
}

__device__ __forceinline__ void mma16816(float* c, const uint32_t* a, const uint32_t* b) {
    asm volatile(
        "mma.sync.aligned.m16n8k16.row.col.f32.f16.f16.f32 "
        "{%0,%1,%2,%3}, {%4,%5,%6,%7}, {%8,%9}, {%0,%1,%2,%3};"
        : "+f"(c[0]), "+f"(c[1]), "+f"(c[2]), "+f"(c[3])
        : "r"(a[0]), "r"(a[1]), "r"(a[2]), "r"(a[3]), "r"(b[0]), "r"(b[1]));
}

// ---------------------------------------------------------------------------
// Prepass kernels
// ---------------------------------------------------------------------------
__global__ void prep_x_kernel(const float4* __restrict__ x, int n4) {
    int i = blockIdx.x * blockDim.x + threadIdx.x;
    if (i < n4) {
        float4 v = x[i];
        __half2 lo = __floats2half2_rn(v.x, v.y);
        __half2 hi = __floats2half2_rn(v.z, v.w);
        union { __half2 h; unsigned u; } a, b;
        a.h = lo; b.h = hi;
        reinterpret_cast<uint2*>(g_Xh)[i] = make_uint2(a.u, b.u);
    }
}

// W1[q][h][n] (n contiguous) -> Wh[q][n][h] (h contiguous), rounded to fp16
__global__ void prep_w_kernel(const float* __restrict__ W1) {
    __shared__ float tile[32][33];
    int q  = blockIdx.z;
    int n0 = blockIdx.x * 32;
    int h0 = blockIdx.y * 32;
    const float* src = W1 + (size_t)q * HIDDEN * HALF_DIM;
#pragma unroll
    for (int r = 0; r < 4; r++) {
        int row = threadIdx.y + r * 8;  // h offset
        tile[row][threadIdx.x] = src[(size_t)(h0 + row) * HALF_DIM + n0 + threadIdx.x];
    }
    __syncthreads();
    __half* dst = g_Wh + (size_t)q * HALF_DIM * HIDDEN;
#pragma unroll
    for (int r = 0; r < 4; r++) {
        int row = threadIdx.y + r * 8;  // n offset
        dst[(size_t)(n0 + row) * HIDDEN + h0 + threadIdx.x] = __float2half_rn(tile[threadIdx.x][row]);
    }
}

__global__ void init_out_kernel(float* __restrict__ out, const float* __restrict__ b2) {
    int i = blockIdx.x * blockDim.x + threadIdx.x;
    if (i < BATCH * NQ) out[i] = b2[i & (NQ - 1)];
}

// ---------------------------------------------------------------------------
// Main GEMM + fused GELU/GEMV epilogue (mma.sync / HMMA path)
// ---------------------------------------------------------------------------
__device__ __forceinline__ void load_stage(uint32_t sb, int s, int chunk,
                                           const __half* Ab, const __half* Bb, int tid) {
    uint32_t a0 = sb + OFF_STAGE + s * STAGE_BYTES;
    uint32_t b0 = a0 + A_STAGE_BYTES;
    const char* asrc = (const char*)Ab + (size_t)chunk * (KC * 2);
    const char* bsrc = (const char*)Bb + (size_t)chunk * (KC * 2);
    // A: 128 rows x 128B = 1024 x 16B transfers
#pragma unroll
    for (int t = 0; t < 8; t++) {
        int o = tid + t * THREADS;      // 0..1023
        int row = o >> 3;
        int kg  = o & 7;
        uint32_t off = row * 128 + kg * 16;
        cp_async16(a0 + SW128(off), asrc + (size_t)row * (HIDDEN * 2) + kg * 16);
    }
    // B: 64 rows x 128B = 512 x 16B transfers
#pragma unroll
    for (int t = 0; t < 4; t++) {
        int o = tid + t * THREADS;      // 0..511
        int row = o >> 3;
        int kg  = o & 7;
        uint32_t off = row * 128 + kg * 16;
        cp_async16(b0 + SW128(off), bsrc + (size_t)row * (HIDDEN * 2) + kg * 16);
    }
}

__global__ void __launch_bounds__(THREADS, 4)
gemm_kernel(const float* __restrict__ b1, const float* __restrict__ W2,
            float* __restrict__ out) {
    extern __shared__ char smem[];
    const uint32_t sb = smem_u32(smem);
    const int tid = threadIdx.x;
    const int wid = tid >> 5;
    const int lid = tid & 31;
    const int wm  = wid >> 1;           // M slab (64 rows), 0..1
    const int wn  = wid & 1;            // N slab (32 cols), 0..1

    // Supertile swizzle: 8(M) x 16(N) CTAs per 128-CTA group; 8x16 groups.
    int cta    = blockIdx.x;
    int super  = cta >> 7;              // 0..127
    int within = cta & 127;
    int m_tile = (super & 7) * 8 + (within & 7);     // 0..63
    int n_tile = (super >> 3) * 16 + (within >> 3);  // 0..255
    int m0     = m_tile * BM;
    int wrow0  = n_tile * BN;                        // = q*1024 + nn
    int q      = n_tile >> 4;
    int nn     = (n_tile & 15) * BN;

    // Epilogue params into smem
    if (tid < BN) {
        ((float*)(smem + OFF_B1))[tid] = b1[q * HALF_DIM + nn + tid];
        ((float*)(smem + OFF_W2))[tid] = W2[q * HALF_DIM + nn + tid];
    }

    const __half* Ab = g_Xh + (size_t)m0 * HIDDEN;
    const __half* Bb = g_Wh + (size_t)wrow0 * HIDDEN;

    // Prologue: fill first stage
    load_stage(sb, 0, 0, Ab, Bb, tid);
    cp_async_commit();

    // acc[mi][ni][4]: mi = 4 x m16 slabs (64 rows), ni = 4 x n8 slabs (32 cols)
    float acc[4][4][4];
#pragma unroll
    for (int mi = 0; mi < 4; mi++)
#pragma unroll
        for (int ni = 0; ni < 4; ni++)
#pragma unroll
            for (int e = 0; e < 4; e++) acc[mi][ni][e] = 0.0f;

    // ldmatrix lane-address components (bytes, pre-swizzle)
    const int a_row_l = lid & 15;                       // m row within 16
    const int a_kb_l  = (lid >> 4) << 4;                // 0 or 16 bytes
    const int b_row_l = ((lid >> 4) << 3) + (lid & 7);  // n row within 16
    const int b_kb_l  = ((lid >> 3) & 1) << 4;          // 0 or 16 bytes

    for (int i = 0; i < NCHUNK; i++) {
        cp_async_wait<0>();
        __syncthreads();

        int jn = i + 1;
        if (jn < NCHUNK) {
            load_stage(sb, jn & 1, jn, Ab, Bb, tid);
            cp_async_commit();
        }

        uint32_t a_base = sb + OFF_STAGE + (i & 1) * STAGE_BYTES;
        uint32_t b_base = a_base + A_STAGE_BYTES;

#pragma unroll
        for (int kk = 0; kk < 4; kk++) {   // 4 x k16 steps per 64-K chunk
            // A fragments: 64 rows (4 x 16)
            uint32_t afr[4][4];
#pragma unroll
            for (int mi = 0; mi < 4; mi++) {
                uint32_t off = (uint32_t)(wm * 64 + mi * 16 + a_row_l) * 128
                             + (uint32_t)(kk * 32 + a_kb_l);
                ldsm4(afr[mi], a_base + SW128(off));
            }
            // B fragments: 32 cols (2 x 16)
            uint32_t bfr[2][4];
#pragma unroll
            for (int nj = 0; nj < 2; nj++) {
                uint32_t off = (uint32_t)(wn * 32 + nj * 16 + b_row_l) * 128
                             + (uint32_t)(kk * 32 + b_kb_l);
                ldsm4(bfr[nj], b_base + SW128(off));
            }
            // 16 MMAs per k-step
#pragma unroll
            for (int mi = 0; mi < 4; mi++)
#pragma unroll
                for (int nj = 0; nj < 2; nj++) {
                    mma16816(acc[mi][nj * 2 + 0], afr[mi], &bfr[nj][0]);
                    mma16816(acc[mi][nj * 2 + 1], afr[mi], &bfr[nj][2]);
                }
        }
    }
    __syncthreads();

    // Epilogue: h = acc + b1; gelu(h) = h * Phi(h); dot with W2; quad-reduce; atomic add.
    const float* b1s = (const float*)(smem + OFF_B1);
    const float* w2s = (const float*)(smem + OFF_W2);
#pragma unroll
    for (int mi = 0; mi < 4; mi++) {
#pragma unroll
        for (int rh = 0; rh < 2; rh++) {
            float v = 0.0f;
#pragma unroll
            for (int ni = 0; ni < 4; ni++) {
                int ncol = wn * 32 + ni * 8 + 2 * (lid & 3);
#pragma unroll
                for (int e = 0; e < 2; e++) {
                    float h = acc[mi][ni][rh * 2 + e] + b1s[ncol + e];
                    v += h * normcdff(h) * w2s[ncol + e];
                }
            }
            v += __shfl_xor_sync(0xFFFFFFFFu, v, 1);
            v += __shfl_xor_sync(0xFFFFFFFFu, v, 2);
            if ((lid & 3) == 0) {
                int mrow = m0 + wm * 64 + mi * 16 + rh * 8 + (lid >> 2);
                atomicAdd(out + (size_t)mrow * NQ + q, v);
            }
        }
    }
}

// ---------------------------------------------------------------------------
// Launch
// ---------------------------------------------------------------------------
extern "C" void kernel_launch(void* const* d_in, const int* in_sizes, int n_in,
                              void* d_out, int out_size) {
    const float* x  = (const float*)d_in[0];
    const float* W1 = (const float*)d_in[1];
    const float* b1 = (const float*)d_in[2];
    const float* W2 = (const float*)d_in[3];
    const float* b2 = (const float*)d_in[4];
    float* out = (float*)d_out;
    (void)in_sizes; (void)n_in; (void)out_size;

    cudaFuncSetAttribute(gemm_kernel, cudaFuncAttributeMaxDynamicSharedMemorySize, SMEM_BYTES);

    int n4 = BATCH * HIDDEN / 4;
    prep_x_kernel<<<(n4 + 255) / 256, 256>>>((const float4*)x, n4);
    prep_w_kernel<<<dim3(HALF_DIM / 32, HIDDEN / 32, NQ), dim3(32, 8)>>>(W1);
    init_out_kernel<<<(BATCH * NQ + 255) / 256, 256>>>(out, b2);
    gemm_kernel<<<(BATCH / BM) * (NQ * HALF_DIM / BN), THREADS, SMEM_BYTES>>>(b1, W2, out);
}